// round 12
// baseline (speedup 1.0000x reference)
#include <cuda_runtime.h>
#include <cstdint>

// GIN_38216619000492: GINConv (eps=0) + 2-layer MLP.
//   h = x + segment_sum(x[src], dst);  hid = relu(h@W1+b1);  out = hid@W2+b2
// N=50000, E=800000, edge_index int32. MLP via mma.sync tf32 (base sm_100).
// R12: CSR rebuild of the aggregation (histogram/scan/reorder, NO atomic
// feature updates) + gather fused into the MLP staging phase. g_h eliminated;
// gather (L2-bound) overlaps GEMM work (tensor/latency-bound) across CTAs.

#define D_IN  64
#define D_H   256
#define D_OUT 64
#define NMAX  50000
#define EMAX  800000

static __device__ int   g_cnt[NMAX];
static __device__ int   g_off[NMAX + 1];
static __device__ int   g_cur[NMAX];
static __device__ int   g_srcs[EMAX];
static __device__ float g_B1[17408];   // W1^T tf32: [n=256][k=64] stride 68
static __device__ float g_B2[16896];   // W2^T tf32: [kh=2][n=64][kk=128] stride 132

__device__ __forceinline__ uint32_t f2tf32(float f) {
    uint32_t u;
    asm("cvt.rna.tf32.f32 %0, %1;" : "=r"(u) : "f"(f));
    return u;
}

__device__ __forceinline__ void mma8(float* c, uint32_t a0, uint32_t a1,
                                     uint32_t a2, uint32_t a3,
                                     uint32_t b0, uint32_t b1) {
    asm volatile(
        "mma.sync.aligned.m16n8k8.row.col.f32.tf32.tf32.f32 "
        "{%0,%1,%2,%3}, {%4,%5,%6,%7}, {%8,%9}, {%0,%1,%2,%3};"
        : "+f"(c[0]), "+f"(c[1]), "+f"(c[2]), "+f"(c[3])
        : "r"(a0), "r"(a1), "r"(a2), "r"(a3), "r"(b0), "r"(b1));
}

// ---------------------------------------------------------------------------
// Kernel 1: zero degree counters + build tf32 weight images.
// ---------------------------------------------------------------------------
__global__ void gin_init(const float* __restrict__ W1,
                         const float* __restrict__ W2, int N) {
    int i = blockIdx.x * blockDim.x + threadIdx.x;
    if (i < N) g_cnt[i] = 0;
    if (i < 16384) {                        // W1[k][n], k<64, n<256
        int k = i >> 8, n = i & 255;
        ((uint32_t*)g_B1)[n * 68 + k] = f2tf32(W1[i]);
    } else if (i < 32768) {                 // W2[k][n], k<256, n<64
        int j = i - 16384;
        int k = j >> 6, n = j & 63;
        int kh = k >> 7, kk = k & 127;
        ((uint32_t*)g_B2)[kh * 8448 + n * 132 + kk] = f2tf32(W2[j]);
    }
}

// ---------------------------------------------------------------------------
// Kernel 2: degree histogram (int atomics, spread addresses -> cheap).
// ---------------------------------------------------------------------------
__global__ void gin_hist(const int* __restrict__ ei, int E) {
    int i = blockIdx.x * blockDim.x + threadIdx.x;
    if (i < E) atomicAdd(&g_cnt[ei[E + i]], 1);
}

// ---------------------------------------------------------------------------
// Kernel 3: single-block exclusive scan -> g_off / g_cur.
// ---------------------------------------------------------------------------
#define SCAN_T 1024
__global__ void gin_scan(int N, int E) {
    __shared__ int ps[SCAN_T];
    const int i = threadIdx.x;
    const int CH = (N + SCAN_T - 1) / SCAN_T;
    const int base = i * CH;
    int sum = 0;
    for (int j = 0; j < CH; j++) {
        int idx = base + j;
        if (idx < N) sum += g_cnt[idx];
    }
    ps[i] = sum;
    __syncthreads();
    for (int d = 1; d < SCAN_T; d <<= 1) {           // Hillis-Steele inclusive
        int other = (i >= d) ? ps[i - d] : 0;
        __syncthreads();
        ps[i] += other;
        __syncthreads();
    }
    int run = ps[i] - sum;                           // exclusive prefix of chunk
    for (int j = 0; j < CH; j++) {
        int idx = base + j;
        if (idx < N) {
            g_off[idx] = run;
            g_cur[idx] = run;
            run += g_cnt[idx];
        }
    }
    if (i == SCAN_T - 1) g_off[N] = E;
}

// ---------------------------------------------------------------------------
// Kernel 4: reorder src indices into dst-sorted buckets.
// ---------------------------------------------------------------------------
__global__ void gin_reorder(const int* __restrict__ ei, int E) {
    int i = blockIdx.x * blockDim.x + threadIdx.x;
    if (i >= E) return;
    int dst = ei[E + i];
    int p = atomicAdd(&g_cur[dst], 1);
    g_srcs[p] = ei[i];
}

// ---------------------------------------------------------------------------
// Kernel 5: FUSED gather + MLP. 64 rows/CTA, 8 warps, 2 CTAs/SM.
// Staging phase = CSR gather: 4 threads/row, each owns a 16-float chunk,
// register-accumulates its node's neighbor rows, adds x[row], writes tf32 hs.
// GEMM structure identical to R11 (validated): GEMM1 mq/nq 2x4; GEMM2 mw/nh
// 4x2 with B2 staged in two k-halves (acc carried -> same numerics).
// SMEM word map (101,632 B):
//   phase1: hs @0 [64][68], B1 @4352 [256][68]
//   phase2: hid @0 [64][260], B2H @16640 [64][132]
//   b1s @25088 [256], b2s @25344 [64].
// ---------------------------------------------------------------------------
#define HS_F    0
#define B1_F    4352
#define HID_F   0
#define B2H_F   16640
#define B1S_F   25088
#define B2S_F   25344
#define SMEM_BYTES (25408 * 4)

__global__ __launch_bounds__(256, 2)
void gin_mlp(const float* __restrict__ x,
             const float* __restrict__ b1, const float* __restrict__ b2,
             float* __restrict__ out, int N) {
    extern __shared__ float s[];
    uint32_t* su = (uint32_t*)s;

    const int t = threadIdx.x;
    const int w = t >> 5;
    const int lane = t & 31;
    const int g = lane >> 2;
    const int tg = lane & 3;
    const int row0 = blockIdx.x * 64;

    // ---- Stage B1 + biases ----
    {
        const float4* g1 = (const float4*)g_B1;
        float4* s1 = (float4*)(s + B1_F);
        #pragma unroll 4
        for (int i = t; i < 4352; i += 256) s1[i] = g1[i];
        if (t < 64) ((float4*)(s + B1S_F))[t] = ((const float4*)b1)[t];
        if (t < 16) ((float4*)(s + B2S_F))[t] = ((const float4*)b2)[t];
    }

    // ---- Fused CSR gather: h = x[row] + sum_{src in N(row)} x[src] ----
    {
        const int r = t >> 2;               // row 0..63
        const int q = t & 3;                // 16-float chunk
        const int gr = row0 + r;
        float4 a0 = make_float4(0.f, 0.f, 0.f, 0.f);
        float4 a1 = a0, a2 = a0, a3 = a0;
        if (gr < N) {
            const int beg = g_off[gr];
            const int end = g_off[gr + 1];
            for (int idx = beg; idx < end; idx++) {
                const float4* xp =
                    (const float4*)(x + (size_t)g_srcs[idx] * D_IN + q * 16);
                float4 v0 = xp[0], v1 = xp[1], v2 = xp[2], v3 = xp[3];
                a0.x += v0.x; a0.y += v0.y; a0.z += v0.z; a0.w += v0.w;
                a1.x += v1.x; a1.y += v1.y; a1.z += v1.z; a1.w += v1.w;
                a2.x += v2.x; a2.y += v2.y; a2.z += v2.z; a2.w += v2.w;
                a3.x += v3.x; a3.y += v3.y; a3.z += v3.z; a3.w += v3.w;
            }
            const float4* xg = (const float4*)(x + (size_t)gr * D_IN + q * 16);
            float4 v0 = xg[0], v1 = xg[1], v2 = xg[2], v3 = xg[3];
            a0.x += v0.x; a0.y += v0.y; a0.z += v0.z; a0.w += v0.w;
            a1.x += v1.x; a1.y += v1.y; a1.z += v1.z; a1.w += v1.w;
            a2.x += v2.x; a2.y += v2.y; a2.z += v2.z; a2.w += v2.w;
            a3.x += v3.x; a3.y += v3.y; a3.z += v3.z; a3.w += v3.w;
        }
        float* hb = s + HS_F + r * 68 + q * 16;
        *(uint4*)(hb + 0)  = make_uint4(f2tf32(a0.x), f2tf32(a0.y), f2tf32(a0.z), f2tf32(a0.w));
        *(uint4*)(hb + 4)  = make_uint4(f2tf32(a1.x), f2tf32(a1.y), f2tf32(a1.z), f2tf32(a1.w));
        *(uint4*)(hb + 8)  = make_uint4(f2tf32(a2.x), f2tf32(a2.y), f2tf32(a2.z), f2tf32(a2.w));
        *(uint4*)(hb + 12) = make_uint4(f2tf32(a3.x), f2tf32(a3.y), f2tf32(a3.z), f2tf32(a3.w));
    }
    __syncthreads();

    // ---- GEMM1: warp = rows [32mq,32mq+32) x cols [64nq,64nq+64) ----
    const int mq = w & 1;
    const int nq = w >> 1;
    float acc[2][8][4];
    #pragma unroll
    for (int b = 0; b < 2; b++)
        #pragma unroll
        for (int nt = 0; nt < 8; nt++)
            #pragma unroll
            for (int j = 0; j < 4; j++) acc[b][nt][j] = 0.f;

    {
        const uint32_t* alo0 = su + HS_F + (32 * mq + g) * 68;
        const uint32_t* ahi0 = alo0 + 8 * 68;
        const uint32_t* alo1 = alo0 + 16 * 68;
        const uint32_t* ahi1 = alo0 + 24 * 68;
        const uint32_t* Bb = su + B1_F + (nq * 64 + g) * 68;
        #pragma unroll
        for (int ks = 0; ks < 8; ks++) {
            int kb = ks * 8;
            uint32_t a0[2], a1[2], a2[2], a3[2];
            a0[0] = alo0[kb + tg];     a1[0] = ahi0[kb + tg];
            a2[0] = alo0[kb + tg + 4]; a3[0] = ahi0[kb + tg + 4];
            a0[1] = alo1[kb + tg];     a1[1] = ahi1[kb + tg];
            a2[1] = alo1[kb + tg + 4]; a3[1] = ahi1[kb + tg + 4];
            #pragma unroll
            for (int c4 = 0; c4 < 2; c4++) {
                uint32_t bv[4][2];
                #pragma unroll
                for (int q = 0; q < 4; q++) {
                    int ntl = c4 * 4 + q;
                    bv[q][0] = Bb[ntl * 8 * 68 + kb + tg];
                    bv[q][1] = Bb[ntl * 8 * 68 + kb + tg + 4];
                }
                #pragma unroll
                for (int q = 0; q < 4; q++) {
                    mma8(acc[0][c4 * 4 + q], a0[0], a1[0], a2[0], a3[0], bv[q][0], bv[q][1]);
                    mma8(acc[1][c4 * 4 + q], a0[1], a1[1], a2[1], a3[1], bv[q][0], bv[q][1]);
                }
            }
        }
    }
    __syncthreads();   // hs/B1 reads done; hid/B2H may overlay them

    // ---- Epilogue 1: hid = tf32(relu(D1 + b1)) ----
    {
        #pragma unroll
        for (int b = 0; b < 2; b++) {
            int r_lo = 32 * mq + 16 * b + g;
            float* h_lo = s + HID_F + r_lo * 260;
            float* h_hi = h_lo + 8 * 260;
            #pragma unroll
            for (int ntl = 0; ntl < 8; ntl++) {
                int col = (nq * 8 + ntl) * 8 + 2 * tg;
                float bb0 = s[B1S_F + col], bb1 = s[B1S_F + col + 1];
                uint2 u0, u1;
                u0.x = f2tf32(fmaxf(acc[b][ntl][0] + bb0, 0.f));
                u0.y = f2tf32(fmaxf(acc[b][ntl][1] + bb1, 0.f));
                u1.x = f2tf32(fmaxf(acc[b][ntl][2] + bb0, 0.f));
                u1.y = f2tf32(fmaxf(acc[b][ntl][3] + bb1, 0.f));
                *(uint2*)(h_lo + col) = u0;
                *(uint2*)(h_hi + col) = u1;
            }
        }
    }
    // ---- Stage B2 half 0 (disjoint from hid) ----
    {
        const float4* gh = (const float4*)g_B2;
        float4* sh = (float4*)(s + B2H_F);
        #pragma unroll 4
        for (int i = t; i < 2112; i += 256) sh[i] = gh[i];
    }
    __syncthreads();

    // ---- GEMM2: rows [16mw,+16) x cols [32nh,+32), two staged k-halves ----
    const int mw = w & 3;
    const int nh = w >> 2;
    float acc2[4][4];
    #pragma unroll
    for (int nt = 0; nt < 4; nt++)
        #pragma unroll
        for (int j = 0; j < 4; j++) acc2[nt][j] = 0.f;

    #pragma unroll
    for (int kh = 0; kh < 2; kh++) {
        if (kh == 1) {
            __syncthreads();    // half-0 reads done
            const float4* gh = (const float4*)(g_B2 + 8448);
            float4* sh = (float4*)(s + B2H_F);
            #pragma unroll 4
            for (int i = t; i < 2112; i += 256) sh[i] = gh[i];
            __syncthreads();
        }
        const uint32_t* arow_lo = su + HID_F + (16 * mw + g) * 260 + kh * 128;
        const uint32_t* arow_hi = arow_lo + 8 * 260;
        const uint32_t* Bb = su + B2H_F + (nh * 32 + g) * 132;
        #pragma unroll 4
        for (int ks = 0; ks < 16; ks++) {
            int kb = ks * 8;
            uint32_t a0 = arow_lo[kb + tg];
            uint32_t a1 = arow_hi[kb + tg];
            uint32_t a2 = arow_lo[kb + tg + 4];
            uint32_t a3 = arow_hi[kb + tg + 4];
            uint32_t bv[4][2];
            #pragma unroll
            for (int q = 0; q < 4; q++) {
                bv[q][0] = Bb[q * 8 * 132 + kb + tg];
                bv[q][1] = Bb[q * 8 * 132 + kb + tg + 4];
            }
            #pragma unroll
            for (int q = 0; q < 4; q++)
                mma8(acc2[q], a0, a1, a2, a3, bv[q][0], bv[q][1]);
        }
    }

    // ---- Epilogue 2: out = D2 + b2 (fp32) ----
    {
        int gr_lo = row0 + 16 * mw + g;
        int gr_hi = gr_lo + 8;
        #pragma unroll
        for (int ntl = 0; ntl < 4; ntl++) {
            int col = nh * 32 + ntl * 8 + 2 * tg;
            float bb0 = s[B2S_F + col], bb1 = s[B2S_F + col + 1];
            if (gr_lo < N) {
                float2 v = make_float2(acc2[ntl][0] + bb0, acc2[ntl][1] + bb1);
                *(float2*)(out + (size_t)gr_lo * D_OUT + col) = v;
            }
            if (gr_hi < N) {
                float2 v = make_float2(acc2[ntl][2] + bb0, acc2[ntl][3] + bb1);
                *(float2*)(out + (size_t)gr_hi * D_OUT + col) = v;
            }
        }
    }
}

// ---------------------------------------------------------------------------
// Launch. Inputs: x[f32], edge_index[i32 2xE], W1, b1, W2, b2.
// ---------------------------------------------------------------------------
extern "C" void kernel_launch(void* const* d_in, const int* in_sizes, int n_in,
                              void* d_out, int out_size) {
    const float* x  = (const float*)d_in[0];
    const int*   ei = (const int*)d_in[1];
    const float* W1 = (const float*)d_in[2];
    const float* b1 = (const float*)d_in[3];
    const float* W2 = (const float*)d_in[4];
    const float* b2 = (const float*)d_in[5];
    float* out = (float*)d_out;

    const int N = in_sizes[0] / D_IN;   // 50000
    const int E = in_sizes[1] / 2;      // 800000

    cudaFuncSetAttribute(gin_mlp, cudaFuncAttributeMaxDynamicSharedMemorySize,
                         SMEM_BYTES);

    gin_init<<<(N + 255) / 256, 256>>>(W1, W2, N);
    gin_hist<<<(E + 255) / 256, 256>>>(ei, E);
    gin_scan<<<1, SCAN_T>>>(N, E);
    gin_reorder<<<(E + 255) / 256, 256>>>(ei, E);
    gin_mlp<<<(N + 63) / 64, 256, SMEM_BYTES>>>(x, b1, b2, out, N);
}

// round 13
// speedup vs baseline: 2.0726x; 2.0726x over previous
#include <cuda_runtime.h>
#include <cstdint>

// GIN_38216619000492: GINConv (eps=0) + 2-layer MLP.
//   h = x + segment_sum(x[src], dst);  hid = relu(h@W1+b1);  out = hid@W2+b2
// N=50000, E=800000, edge_index int32. MLP via mma.sync tf32 (base sm_100).
// R13: consolidation. R8's proven MLP (41.6us) + R5's proven scatter (~33us)
// + zero-fill instead of copy (g_h write-only) + "+x" fused into MLP staging
// + weight prep merged into the zero kernel. CSR route abandoned (build cost
// ~= scatter cost; fused gather spilled registers under the (256,2) cap).

#define D_IN  64
#define D_H   256
#define D_OUT 64
#define NMAX  50000

static __device__ float g_h[(size_t)NMAX * D_IN];
static __device__ float g_B1[17408];   // W1^T tf32 image: [n=256][k=64], stride 68
static __device__ float g_B2[16640];   // W2^T tf32 image: [n=64][k=256], stride 260

__device__ __forceinline__ uint32_t f2tf32(float f) {
    uint32_t u;
    asm("cvt.rna.tf32.f32 %0, %1;" : "=r"(u) : "f"(f));
    return u;
}

__device__ __forceinline__ void mma8(float* c, uint32_t a0, uint32_t a1,
                                     uint32_t a2, uint32_t a3,
                                     uint32_t b0, uint32_t b1) {
    asm volatile(
        "mma.sync.aligned.m16n8k8.row.col.f32.tf32.tf32.f32 "
        "{%0,%1,%2,%3}, {%4,%5,%6,%7}, {%8,%9}, {%0,%1,%2,%3};"
        : "+f"(c[0]), "+f"(c[1]), "+f"(c[2]), "+f"(c[3])
        : "r"(a0), "r"(a1), "r"(a2), "r"(a3), "r"(b0), "r"(b1));
}

// ---------------------------------------------------------------------------
// Kernel 1: zero g_h + build tf32 weight images (single launch).
// ---------------------------------------------------------------------------
__global__ void gin_init(const float* __restrict__ W1,
                         const float* __restrict__ W2, int n4) {
    int i = blockIdx.x * blockDim.x + threadIdx.x;
    if (i < n4) ((float4*)g_h)[i] = make_float4(0.f, 0.f, 0.f, 0.f);
    if (i < 16384) {                        // W1[k][n], k<64, n<256
        int k = i >> 8, n = i & 255;
        ((uint32_t*)g_B1)[n * 68 + k] = f2tf32(W1[i]);
    } else if (i < 32768) {                 // W2[k][n], k<256, n<64
        int j = i - 16384;
        int k = j >> 6, n = j & 63;
        ((uint32_t*)g_B2)[n * 260 + k] = f2tf32(W2[j]);
    }
}

// ---------------------------------------------------------------------------
// Kernel 2: scatter-add, red.global.add.v4.f32, 16 threads/edge (proven;
// at the L2 atomic-op floor).
// ---------------------------------------------------------------------------
__global__ void gin_scatter(const float* __restrict__ x,
                            const int* __restrict__ ei, int E) {
    int w = blockIdx.x * blockDim.x + threadIdx.x;
    int e = w >> 4;
    if (e >= E) return;
    int c = (w & 15) << 2;
    int src = ei[e];
    int dst = ei[E + e];
    float4 v = *(const float4*)(x + (size_t)src * D_IN + c);
    float* o = g_h + (size_t)dst * D_IN + c;
    asm volatile("red.global.add.v4.f32 [%0], {%1, %2, %3, %4};"
                 :: "l"(o), "f"(v.x), "f"(v.y), "f"(v.z), "f"(v.w)
                 : "memory");
}

// ---------------------------------------------------------------------------
// Kernel 3: fused MLP, tf32 mma.sync. 128 rows/CTA, 16 warps (512 thr).
// EXACT R8 structure (41.6us proven): GEMM1 warp w -> mw=w&7 rows, nh=w>>3
// n-half, 16 n-tiles chunked 2x8; GEMM2 mw/nh with 4 tiles. Only change:
// staging reads x + g_h (g_h is now agg-only).
// SMEM layout (205,568 B, validated):
//   phase1: hs @0 [128][68], B1 @8704 [256][68]
//   phase2: hid rows 0..95 @0 (stride 260), rows 96..127 @42752
//   B2 @26112 [64][260]; b1s @51072; b2s @51328.
// ---------------------------------------------------------------------------
#define HS_F    0
#define B1_F    8704
#define HID0_F  0
#define B2_F    26112
#define HID1_F  42752
#define B1S_F   51072
#define B2S_F   51328
#define SMEM_BYTES (51392 * 4)

__device__ __forceinline__ int hid_off(int r) {
    return (r < 96) ? (HID0_F + r * 260) : (HID1_F + (r - 96) * 260);
}

__global__ __launch_bounds__(512, 1)
void gin_mlp(const float* __restrict__ x,
             const float* __restrict__ b1, const float* __restrict__ b2,
             float* __restrict__ out, int N) {
    extern __shared__ float s[];
    uint32_t* su = (uint32_t*)s;

    const int t = threadIdx.x;
    const int w = t >> 5;
    const int mw = w & 7;         // m-group: rows 16mw..16mw+16
    const int nh = w >> 3;        // n-half
    const int lane = t & 31;
    const int g = lane >> 2;      // group id (0..7)
    const int tg = lane & 3;      // thread-in-group (0..3)
    const int row0 = blockIdx.x * 128;

    // ---- Stage B1, B2, biases ----
    {
        const float4* g1 = (const float4*)g_B1;
        const float4* g2 = (const float4*)g_B2;
        float4* s1 = (float4*)(s + B1_F);
        float4* s2 = (float4*)(s + B2_F);
        #pragma unroll 4
        for (int i = t; i < 4352; i += 512) s1[i] = g1[i];
        #pragma unroll 4
        for (int i = t; i < 4160; i += 512) s2[i] = g2[i];
        if (t < 64) ((float4*)(s + B1S_F))[t] = ((const float4*)b1)[t];
        if (t < 16) ((float4*)(s + B2S_F))[t] = ((const float4*)b2)[t];
    }

    // ---- Stage A1 = tf32(x + g_h) [128][68] ----
    #pragma unroll 4
    for (int i = t; i < 2048; i += 512) {          // 128 rows x 16 float4
        int r = i >> 4, k4 = (i & 15) << 2;
        float4 v = make_float4(0.f, 0.f, 0.f, 0.f);
        int gr = row0 + r;
        if (gr < N) {
            float4 xv = *(const float4*)(x   + (size_t)gr * D_IN + k4);
            float4 hv = *(const float4*)(g_h + (size_t)gr * D_IN + k4);
            v = make_float4(xv.x + hv.x, xv.y + hv.y, xv.z + hv.z, xv.w + hv.w);
        }
        uint4 u = make_uint4(f2tf32(v.x), f2tf32(v.y), f2tf32(v.z), f2tf32(v.w));
        *(uint4*)(s + HS_F + r * 68 + k4) = u;
    }
    __syncthreads();

    // ---- GEMM1: rows [16mw,16mw+16) x cols [nh*128, nh*128+128) ----
    float acc[16][4];
    #pragma unroll
    for (int nt = 0; nt < 16; nt++)
        #pragma unroll
        for (int j = 0; j < 4; j++) acc[nt][j] = 0.f;

    {
        const uint32_t* arow_lo = su + HS_F + (16 * mw + g) * 68;
        const uint32_t* arow_hi = arow_lo + 8 * 68;
        const uint32_t* Bb = su + B1_F + (nh * 128 + g) * 68;   // n = nh*128 + ntl*8 + g
        #pragma unroll
        for (int ks = 0; ks < 8; ks++) {
            int kb = ks * 8;
            uint32_t a0 = arow_lo[kb + tg];
            uint32_t a1 = arow_hi[kb + tg];
            uint32_t a2 = arow_lo[kb + tg + 4];
            uint32_t a3 = arow_hi[kb + tg + 4];
            #pragma unroll
            for (int c8 = 0; c8 < 2; c8++) {
                uint32_t bv[8][2];
                #pragma unroll
                for (int q = 0; q < 8; q++) {
                    int ntl = c8 * 8 + q;
                    bv[q][0] = Bb[ntl * 8 * 68 + kb + tg];
                    bv[q][1] = Bb[ntl * 8 * 68 + kb + tg + 4];
                }
                #pragma unroll
                for (int q = 0; q < 8; q++)
                    mma8(acc[c8 * 8 + q], a0, a1, a2, a3, bv[q][0], bv[q][1]);
            }
        }
    }
    __syncthreads();   // all reads of hs/B1 done; hid may alias them

    // ---- Epilogue 1: hid = tf32(relu(D1 + b1)) ----
    {
        const int r_lo = 16 * mw + g;
        float* h_lo = s + hid_off(r_lo);
        float* h_hi = s + hid_off(r_lo + 8);
        #pragma unroll
        for (int ntl = 0; ntl < 16; ntl++) {
            int col = (nh * 16 + ntl) * 8 + 2 * tg;
            float bb0 = s[B1S_F + col], bb1 = s[B1S_F + col + 1];
            uint2 u0, u1;
            u0.x = f2tf32(fmaxf(acc[ntl][0] + bb0, 0.f));
            u0.y = f2tf32(fmaxf(acc[ntl][1] + bb1, 0.f));
            u1.x = f2tf32(fmaxf(acc[ntl][2] + bb0, 0.f));
            u1.y = f2tf32(fmaxf(acc[ntl][3] + bb1, 0.f));
            *(uint2*)(h_lo + col) = u0;
            *(uint2*)(h_hi + col) = u1;
        }
    }
    __syncthreads();

    // ---- GEMM2: rows [16mw,16mw+16) x cols [32nh,32nh+32) ----
    float acc2[4][4];
    #pragma unroll
    for (int nt = 0; nt < 4; nt++)
        #pragma unroll
        for (int j = 0; j < 4; j++) acc2[nt][j] = 0.f;

    {
        const uint32_t* arow_lo = su + hid_off(16 * mw + g);
        const uint32_t* arow_hi = su + hid_off(16 * mw + g + 8);
        const uint32_t* Bb = su + B2_F + (nh * 32 + g) * 260;   // n = nh*32 + ntl*8 + g
        #pragma unroll 4
        for (int ks = 0; ks < 32; ks++) {
            int kb = ks * 8;
            uint32_t a0 = arow_lo[kb + tg];
            uint32_t a1 = arow_hi[kb + tg];
            uint32_t a2 = arow_lo[kb + tg + 4];
            uint32_t a3 = arow_hi[kb + tg + 4];
            uint32_t bv[4][2];
            #pragma unroll
            for (int q = 0; q < 4; q++) {
                bv[q][0] = Bb[q * 8 * 260 + kb + tg];
                bv[q][1] = Bb[q * 8 * 260 + kb + tg + 4];
            }
            #pragma unroll
            for (int q = 0; q < 4; q++)
                mma8(acc2[q], a0, a1, a2, a3, bv[q][0], bv[q][1]);
        }
    }

    // ---- Epilogue 2: out = D2 + b2 (fp32) ----
    {
        int gr_lo = row0 + 16 * mw + g;
        int gr_hi = gr_lo + 8;
        #pragma unroll
        for (int ntl = 0; ntl < 4; ntl++) {
            int col = (nh * 4 + ntl) * 8 + 2 * tg;
            float bb0 = s[B2S_F + col], bb1 = s[B2S_F + col + 1];
            if (gr_lo < N) {
                float2 v = make_float2(acc2[ntl][0] + bb0, acc2[ntl][1] + bb1);
                *(float2*)(out + (size_t)gr_lo * D_OUT + col) = v;
            }
            if (gr_hi < N) {
                float2 v = make_float2(acc2[ntl][2] + bb0, acc2[ntl][3] + bb1);
                *(float2*)(out + (size_t)gr_hi * D_OUT + col) = v;
            }
        }
    }
}

// ---------------------------------------------------------------------------
// Launch. Inputs: x[f32], edge_index[i32 2xE], W1, b1, W2, b2.
// ---------------------------------------------------------------------------
extern "C" void kernel_launch(void* const* d_in, const int* in_sizes, int n_in,
                              void* d_out, int out_size) {
    const float* x  = (const float*)d_in[0];
    const int*   ei = (const int*)d_in[1];
    const float* W1 = (const float*)d_in[2];
    const float* b1 = (const float*)d_in[3];
    const float* W2 = (const float*)d_in[4];
    const float* b2 = (const float*)d_in[5];
    float* out = (float*)d_out;

    const int N = in_sizes[0] / D_IN;   // 50000
    const int E = in_sizes[1] / 2;      // 800000

    cudaFuncSetAttribute(gin_mlp, cudaFuncAttributeMaxDynamicSharedMemorySize,
                         SMEM_BYTES);

    int n4 = N * (D_IN / 4);
    gin_init<<<(n4 + 255) / 256, 256>>>(W1, W2, n4);

    int work = E * 16;
    gin_scatter<<<(work + 255) / 256, 256>>>(x, ei, E);

    gin_mlp<<<(N + 127) / 128, 512, SMEM_BYTES>>>(x, b1, b2, out, N);
}